// round 13
// baseline (speedup 1.0000x reference)
#include <cuda_runtime.h>
#include <cuda_fp16.h>
#include <cstdint>

// Fixed shapes
#define BB    2
#define NPTS  20000
#define MM    4096
#define SS    2
#define KK    25
#define JJ    64
#define PTS   16     // points per compute block
#define NTHR  256
#define GTHR  1024   // gather threads (32 warps)
#define NWARP 32
#define IPW   8      // items per warp per pass
#define IPB   2048   // items per gather block
#define PASSES (IPB / (NWARP * IPW))     // 8
#define NITEMS (BB * MM * 50)            // 409600 items
#define GBLKS  ((NITEMS / IPB) * 2)      // 400 blocks (ch fastest)

// Dynamic smem layout (bytes) - gather
#define SM_TAB    0                      // uint2[20000]          160000
#define SM_STG    160000                 // per warp 4 q-blocks * 136 uint * 4B
#define WSTRIDE   2176
#define QSTRIDE   136
#define SM_TOTAL  229632

// Static device scratch
__device__ __align__(16) __half g_xfh[BB * 2 * NPTS * 4]; // [b][chhalf][n][4ch]
__device__ __align__(16) int    g_base[NITEMS];           // per-item gmem base
__device__ __align__(16) float  g_nf[BB * MM * 50 * 8];
__device__ __align__(16) float  g_cwP[KK * 2 * 64 * 4];
__device__ __align__(16) float  g_w0P[32 * 128 * 4];
__device__ __align__(16) float  g_w1P[32 * 256 * 4];
__device__ float g_wsum[64 * 2];

// ---------------------------------------------------------------------------
// f32x2 packed helpers
// ---------------------------------------------------------------------------
__device__ __forceinline__ unsigned long long ffma2_f32x2(
    unsigned long long a, unsigned long long b, unsigned long long c) {
    unsigned long long d;
    asm("fma.rn.f32x2 %0, %1, %2, %3;" : "=l"(d) : "l"(a), "l"(b), "l"(c));
    return d;
}
__device__ __forceinline__ unsigned long long pack_f32x2(float lo, float hi) {
    unsigned long long d;
    asm("mov.b64 %0, {%1, %2};" : "=l"(d) : "f"(lo), "f"(hi));
    return d;
}
__device__ __forceinline__ float2 unpack_f32x2(unsigned long long v) {
    float lo, hi;
    asm("mov.b64 {%0, %1}, %2;" : "=f"(lo), "=f"(hi) : "l"(v));
    return make_float2(lo, hi);
}

// ---------------------------------------------------------------------------
// prep: gather table, per-item bases, packed weights, wsum, passthrough
// ---------------------------------------------------------------------------
__global__ void prep_kernel(const float* __restrict__ xyz,
                            const float* __restrict__ feat,
                            const float* __restrict__ new_xyz,
                            const float* __restrict__ conv_w,
                            const float* __restrict__ w0,
                            const float* __restrict__ w1,
                            float* __restrict__ out) {
    int i = blockIdx.x * blockDim.x + threadIdx.x;

    if (i < BB * NPTS) {
        const int b = i / NPTS;
        const int n = i - b * NPTS;
        float c[8];
        c[0] = xyz[i * 3 + 0];
        c[1] = xyz[i * 3 + 1];
#pragma unroll
        for (int q = 0; q < 6; q++) c[2 + q] = feat[i * 6 + q];

        __half2* lo = reinterpret_cast<__half2*>(g_xfh + ((size_t)(b * 2 + 0) * NPTS + n) * 4);
        __half2* hi = reinterpret_cast<__half2*>(g_xfh + ((size_t)(b * 2 + 1) * NPTS + n) * 4);
        lo[0] = __floats2half2_rn(c[0], c[1]);
        lo[1] = __floats2half2_rn(c[2], c[3]);
        hi[0] = __floats2half2_rn(c[4], c[5]);
        hi[1] = __floats2half2_rn(c[6], c[7]);
    }
    if (i < NITEMS) {
        const int pid = i / 50;
        const int sk  = i - pid * 50;
        const int s   = (sk >= 25) ? 1 : 0;
        const int k   = sk - s * 25;
        const int b   = pid >> 12;
        const int m   = pid & (MM - 1);
        g_base[i] = (((s * BB + b) * MM + m) * KK + k) * JJ;
    }
    if (i < KK * 2 * 64 * 4) {
        int cc = i & 3;
        int o  = (i >> 2) & 63;
        int t  = i >> 8;
        int c4 = t & 1;
        int k  = t >> 1;
        g_cwP[i] = conv_w[o * 200 + (c4 * 4 + cc) * 25 + k];
    }
    if (i < 32 * 128 * 4) {
        int cc = i & 3;
        int o  = (i >> 2) & 127;
        int c4 = i >> 9;
        g_w0P[i] = w0[o * 128 + c4 * 4 + cc];
    }
    if (i < 32 * 256 * 4) {
        int cc = i & 3;
        int o  = (i >> 2) & 255;
        int c4 = i >> 10;
        g_w1P[i] = w1[o * 128 + c4 * 4 + cc];
    }
    if (i < 128) {
        int o = i >> 1, c = i & 1;
        float s = 0.f;
#pragma unroll
        for (int k = 0; k < KK; k++) s += conv_w[o * 200 + c * 25 + k];
        g_wsum[i] = s;
    }
    if (i < BB * MM * 3) {
        out[i] = new_xyz[i];
    }
}

// Pack (idx, weight) into one uint: lo16 = idx, hi16 = fp16 weight
__device__ __forceinline__ unsigned pack_iw(int iv, float wv) {
    return (unsigned)(unsigned short)iv |
           ((unsigned)__half_as_ushort(__float2half_rn(wv)) << 16);
}

// ---------------------------------------------------------------------------
// Gather v8 (byte-identical to R10/R12): precomputed bases, pipelined
// prefetch, packed staging, f32x2 dual FMA.
// ---------------------------------------------------------------------------
__global__ __launch_bounds__(GTHR)
void gather_kernel(const int*   __restrict__ idx,
                   const float* __restrict__ weight) {

    extern __shared__ __align__(16) char smem[];
    uint2*    s_tab = reinterpret_cast<uint2*>(smem + SM_TAB);
    unsigned* stg   = reinterpret_cast<unsigned*>(smem + SM_STG + threadIdx.x / 32 * WSTRIDE);

    const int tid  = threadIdx.x;
    const int lane = tid & 31;
    const int blk  = blockIdx.x;
    const int ch   = blk & 1;
    const int ib   = blk >> 1;

    const int b0 = (ib * IPB) / (MM * 50);

    {
        const uint2* gt = reinterpret_cast<const uint2*>(g_xfh) + (size_t)(b0 * 2 + ch) * NPTS;
        for (int i = tid; i < NPTS; i += GTHR) s_tab[i] = gt[i];
    }
    __syncthreads();

    const int sq  = lane >> 3;
    const int sjl = (lane >> 1) & 3;
    const int seo = (lane & 1) * 2;
    const int woff = sq * QSTRIDE + sjl * 4 + seo;

    const int it  = lane >> 2;
    const int jl4 = lane & 3;
    const unsigned* crow = stg + it * 16 + jl4 * 4;

    const int wbase = ib * IPB + (tid >> 5) * IPW;

    int bc[IPW], bn[IPW];
    uint2 pf[IPW];
    {
#pragma unroll
        for (int t = 0; t < IPW; t++) bc[t] = g_base[wbase + t];
#pragma unroll
        for (int t = 0; t < IPW; t++) {
            const int2   iv = reinterpret_cast<const int2*>(idx + bc[t])[lane];
            const float2 wv = reinterpret_cast<const float2*>(weight + bc[t])[lane];
            pf[t] = make_uint2(pack_iw(iv.x, wv.x), pack_iw(iv.y, wv.y));
        }
#pragma unroll
        for (int t = 0; t < IPW; t++) bc[t] = g_base[wbase + NWARP * IPW + t];
    }

    for (int p = 0; p < PASSES; p++) {
#pragma unroll
        for (int t = 0; t < IPW; t++)
            *reinterpret_cast<uint2*>(stg + woff + t * 16) = pf[t];
        __syncwarp();

        if (p + 2 < PASSES) {
            const int nb = wbase + (p + 2) * (NWARP * IPW);
#pragma unroll
            for (int t = 0; t < IPW; t++) bn[t] = g_base[nb + t];
        }

        if (p + 1 < PASSES) {
#pragma unroll
            for (int t = 0; t < IPW; t++) {
                const int2   iv = reinterpret_cast<const int2*>(idx + bc[t])[lane];
                const float2 wv = reinterpret_cast<const float2*>(weight + bc[t])[lane];
                pf[t] = make_uint2(pack_iw(iv.x, wv.x), pack_iw(iv.y, wv.y));
            }
        }

        unsigned long long acc01 = 0ull, acc23 = 0ull;
#pragma unroll
        for (int q = 0; q < 4; q++) {
            const uint4 pk = *reinterpret_cast<const uint4*>(crow + q * QSTRIDE);
#pragma unroll
            for (int e = 0; e < 4; e++) {
                const unsigned v = (e == 0) ? pk.x : (e == 1) ? pk.y : (e == 2) ? pk.z : pk.w;
                const uint2 row = s_tab[v & 0xFFFFu];
                const float wv  = __half2float(__ushort_as_half((unsigned short)(v >> 16)));
                const float2 f0 = __half22float2(*reinterpret_cast<const __half2*>(&row.x));
                const float2 f1 = __half22float2(*reinterpret_cast<const __half2*>(&row.y));
                const unsigned long long wp = pack_f32x2(wv, wv);
                acc01 = ffma2_f32x2(wp, pack_f32x2(f0.x, f0.y), acc01);
                acc23 = ffma2_f32x2(wp, pack_f32x2(f1.x, f1.y), acc23);
            }
        }

        float4 acc;
        {
            const float2 a = unpack_f32x2(acc01);
            const float2 b = unpack_f32x2(acc23);
            acc = make_float4(a.x, a.y, b.x, b.y);
        }

#pragma unroll
        for (int msk = 1; msk <= 2; msk <<= 1) {
            acc.x += __shfl_xor_sync(0xffffffffu, acc.x, msk);
            acc.y += __shfl_xor_sync(0xffffffffu, acc.y, msk);
            acc.z += __shfl_xor_sync(0xffffffffu, acc.z, msk);
            acc.w += __shfl_xor_sync(0xffffffffu, acc.w, msk);
        }
        if (jl4 == 0) {
            const int git = wbase + p * (NWARP * IPW) + it;
            *reinterpret_cast<float4*>(g_nf + (size_t)git * 8 + ch * 4) = acc;
        }

#pragma unroll
        for (int t = 0; t < IPW; t++) bc[t] = bn[t];
        __syncwarp();
    }
}

// ---------------------------------------------------------------------------
// Compute kernel v4: natural layouts (R10 structure) + FFMA2 over CHANNEL
// pairs. Activations reinterpret as ulonglong2; weights already channel-
// consecutive in packed layouts; final lo+hi fold per output.
// ---------------------------------------------------------------------------
__global__ __launch_bounds__(NTHR) void compute_kernel(
    const float* __restrict__ new_xyz,
    const float* __restrict__ conv_b,
    const float* __restrict__ mlp_b0,
    const float* __restrict__ mlp_b1,
    float* __restrict__ out) {

    __shared__ __align__(16) float s_buf[PTS * 50 * 8];   // nf natural; later h
    __shared__ __align__(16) float s_x[PTS * 128];        // conv out natural
    __shared__ float s_c[PTS * 2];

    const int tid  = threadIdx.x;
    const int warp = tid >> 5;
    const int lane = tid & 31;
    const int blk  = blockIdx.x;

    if (tid < PTS * 2) {
        int p = tid >> 1, c = tid & 1;
        s_c[tid] = new_xyz[(size_t)(blk * PTS + p) * 3 + c];
    }

    {   // straight coalesced nf load (no interleave)
        float4* sb4 = reinterpret_cast<float4*>(s_buf);
        const float4* g4 = reinterpret_cast<const float4*>(g_nf) + (size_t)blk * (PTS * 100);
        for (int i = tid; i < PTS * 100; i += NTHR) sb4[i] = g4[i];
    }
    __syncthreads();

    // ---- Phase B: conv 200->64 per scale; FFMA2 channel pairs ----
    {
        const int o  = lane + (warp & 1) * 32;   // 0..63
        const int pq = warp >> 1;                // 0..3, 4 points each

        const float ws0 = g_wsum[o * 2 + 0];
        const float ws1 = g_wsum[o * 2 + 1];
        const float cb  = conv_b[o];

        float init[4];
#pragma unroll
        for (int pp = 0; pp < 4; pp++) {
            const float cx = s_c[(pq * 4 + pp) * 2 + 0];
            const float cy = s_c[(pq * 4 + pp) * 2 + 1];
            init[pp] = cb - ws0 * cx - ws1 * cy;
        }

        unsigned long long acc[SS][4];
#pragma unroll
        for (int s = 0; s < SS; s++)
#pragma unroll
            for (int pp = 0; pp < 4; pp++) acc[s][pp] = 0ull;

        for (int k = 0; k < KK; k++) {
            const ulonglong2 wl = *reinterpret_cast<const ulonglong2*>(
                g_cwP + (size_t)((k * 2 + 0) * 64 + o) * 4);   // pairs {c0c1},{c2c3}
            const ulonglong2 wh = *reinterpret_cast<const ulonglong2*>(
                g_cwP + (size_t)((k * 2 + 1) * 64 + o) * 4);   // pairs {c4c5},{c6c7}
#pragma unroll
            for (int s = 0; s < SS; s++) {
#pragma unroll
                for (int pp = 0; pp < 4; pp++) {
                    const float* base = s_buf + ((pq * 4 + pp) * 50 + s * 25 + k) * 8;
                    const ulonglong2 a0 = *reinterpret_cast<const ulonglong2*>(base);
                    const ulonglong2 a1 = *reinterpret_cast<const ulonglong2*>(base + 4);
                    unsigned long long a = acc[s][pp];
                    a = ffma2_f32x2(wl.x, a0.x, a);
                    a = ffma2_f32x2(wl.y, a0.y, a);
                    a = ffma2_f32x2(wh.x, a1.x, a);
                    a = ffma2_f32x2(wh.y, a1.y, a);
                    acc[s][pp] = a;
                }
            }
        }
#pragma unroll
        for (int s = 0; s < SS; s++)
#pragma unroll
            for (int pp = 0; pp < 4; pp++) {
                const float2 v = unpack_f32x2(acc[s][pp]);
                s_x[(pq * 4 + pp) * 128 + s * 64 + o] =
                    fmaxf(v.x + v.y + init[pp], 0.f);
            }
    }
    __syncthreads();

    // ---- Phase C: mlp0 128->128; FFMA2 channel pairs ----
    {
        const int o  = lane + (warp & 3) * 32;   // 0..127
        const int p0 = (warp >> 2) * 8;          // 0 or 8

        unsigned long long acc[8];
#pragma unroll
        for (int pp = 0; pp < 8; pp++) acc[pp] = 0ull;

        for (int c4 = 0; c4 < 32; c4++) {
            const ulonglong2 wv = *reinterpret_cast<const ulonglong2*>(
                g_w0P + (size_t)(c4 * 128 + o) * 4);
#pragma unroll
            for (int pp = 0; pp < 8; pp++) {
                const ulonglong2 a = *reinterpret_cast<const ulonglong2*>(
                    s_x + (p0 + pp) * 128 + c4 * 4);
                unsigned long long t = acc[pp];
                t = ffma2_f32x2(wv.x, a.x, t);
                t = ffma2_f32x2(wv.y, a.y, t);
                acc[pp] = t;
            }
        }
        const float b = mlp_b0[o];
        __syncthreads();   // s_buf (nf) reads finished; safe to overwrite
#pragma unroll
        for (int pp = 0; pp < 8; pp++) {
            const float2 v = unpack_f32x2(acc[pp]);
            s_buf[(p0 + pp) * 128 + o] = fmaxf(v.x + v.y + b, 0.f);
        }
    }
    __syncthreads();

    // ---- Phase D: mlp1 128->256 + store; FFMA2 channel pairs ----
    {
        const int o  = lane + (warp & 3) * 32;   // 0..127 (+128 second half)
        const int p0 = (warp >> 2) * 8;

        unsigned long long acc0[8], acc1[8];
#pragma unroll
        for (int pp = 0; pp < 8; pp++) { acc0[pp] = 0ull; acc1[pp] = 0ull; }

        for (int c4 = 0; c4 < 32; c4++) {
            const ulonglong2 wa = *reinterpret_cast<const ulonglong2*>(
                g_w1P + (size_t)(c4 * 256 + o) * 4);
            const ulonglong2 wb = *reinterpret_cast<const ulonglong2*>(
                g_w1P + (size_t)(c4 * 256 + o + 128) * 4);
#pragma unroll
            for (int pp = 0; pp < 8; pp++) {
                const ulonglong2 a = *reinterpret_cast<const ulonglong2*>(
                    s_buf + (p0 + pp) * 128 + c4 * 4);
                unsigned long long t0 = acc0[pp];
                unsigned long long t1 = acc1[pp];
                t0 = ffma2_f32x2(wa.x, a.x, t0);
                t1 = ffma2_f32x2(wb.x, a.x, t1);
                t0 = ffma2_f32x2(wa.y, a.y, t0);
                t1 = ffma2_f32x2(wb.y, a.y, t1);
                acc0[pp] = t0;
                acc1[pp] = t1;
            }
        }
        const float ba = mlp_b1[o];
        const float bb = mlp_b1[o + 128];
        const size_t ob = (size_t)BB * MM * 3;
#pragma unroll
        for (int pp = 0; pp < 8; pp++) {
            const int pid = blk * PTS + p0 + pp;
            const float2 v0 = unpack_f32x2(acc0[pp]);
            const float2 v1 = unpack_f32x2(acc1[pp]);
            out[ob + (size_t)pid * 256 + o]       = fmaxf(v0.x + v0.y + ba, 0.f);
            out[ob + (size_t)pid * 256 + o + 128] = fmaxf(v1.x + v1.y + bb, 0.f);
        }
    }
}

// ---------------------------------------------------------------------------
extern "C" void kernel_launch(void* const* d_in, const int* in_sizes, int n_in,
                              void* d_out, int out_size) {
    const float* xyz     = (const float*)d_in[0];
    const float* feature = (const float*)d_in[1];
    const float* new_xyz = (const float*)d_in[2];
    const int*   idx     = (const int*)  d_in[3];
    const float* weight  = (const float*)d_in[4];
    const float* conv_w  = (const float*)d_in[5];
    const float* conv_b  = (const float*)d_in[6];
    const float* mlp_w0  = (const float*)d_in[7];
    const float* mlp_b0  = (const float*)d_in[8];
    const float* mlp_w1  = (const float*)d_in[9];
    const float* mlp_b1  = (const float*)d_in[10];
    float* out = (float*)d_out;

    (void)in_sizes; (void)n_in; (void)out_size;

    cudaFuncSetAttribute(gather_kernel,
                         cudaFuncAttributeMaxDynamicSharedMemorySize,
                         SM_TOTAL);

    prep_kernel<<<(NITEMS + NTHR - 1) / NTHR, NTHR>>>(
        xyz, feature, new_xyz, conv_w, mlp_w0, mlp_w1, out);

    gather_kernel<<<GBLKS, GTHR, SM_TOTAL>>>(idx, weight);

    compute_kernel<<<(BB * MM) / PTS, NTHR>>>(
        new_xyz, conv_b, mlp_b0, mlp_b1, out);
}

// round 14
// speedup vs baseline: 1.2371x; 1.2371x over previous
#include <cuda_runtime.h>
#include <cuda_fp16.h>
#include <cstdint>

// Fixed shapes
#define BB    2
#define NPTS  20000
#define MM    4096
#define SS    2
#define KK    25
#define JJ    64
#define PTS   16     // points per compute block
#define NTHR  256
#define GTHR  1024   // gather threads (32 warps)
#define NWARP 32
#define IPW   8      // items per warp per pass
#define IPP   (NWARP * IPW)              // 256 items per pass
#define NITEMS (BB * MM * 50)            // 409600 items
#define SEGPASS 800                      // passes per (b) segment (204800/256)
#define GBLKS  296                       // 2 exact waves, 74 blocks per (b,ch)
#define MAXPASS 11

// Dynamic smem layout (bytes) - gather
#define SM_TAB    0                      // uint2[20000]          160000
#define SM_STG    160000                 // per warp 4 q-blocks * 136 uint * 4B
#define WSTRIDE   2176
#define QSTRIDE   136
#define SM_TOTAL  229632

// Static device scratch
__device__ __align__(16) __half g_xfh[BB * 2 * NPTS * 4]; // [b][chhalf][n][4ch]
__device__ __align__(16) int    g_base[NITEMS];           // per-item gmem base
__device__ __align__(16) float  g_nf[BB * MM * 50 * 8];
__device__ __align__(16) float  g_cwP[KK * 2 * 64 * 4];
__device__ __align__(16) float  g_w0P[32 * 128 * 4];
__device__ __align__(16) float  g_w1P[32 * 256 * 4];
__device__ float g_wsum[64 * 2];

// ---------------------------------------------------------------------------
// f32x2 packed helpers
// ---------------------------------------------------------------------------
__device__ __forceinline__ unsigned long long ffma2_f32x2(
    unsigned long long a, unsigned long long b, unsigned long long c) {
    unsigned long long d;
    asm("fma.rn.f32x2 %0, %1, %2, %3;" : "=l"(d) : "l"(a), "l"(b), "l"(c));
    return d;
}
__device__ __forceinline__ unsigned long long pack_f32x2(float lo, float hi) {
    unsigned long long d;
    asm("mov.b64 %0, {%1, %2};" : "=l"(d) : "f"(lo), "f"(hi));
    return d;
}
__device__ __forceinline__ float2 unpack_f32x2(unsigned long long v) {
    float lo, hi;
    asm("mov.b64 {%0, %1}, %2;" : "=f"(lo), "=f"(hi) : "l"(v));
    return make_float2(lo, hi);
}

// ---------------------------------------------------------------------------
// prep (merged, measured 7.1us): table, bases, packed weights, wsum, copy
// ---------------------------------------------------------------------------
__global__ void prep_kernel(const float* __restrict__ xyz,
                            const float* __restrict__ feat,
                            const float* __restrict__ new_xyz,
                            const float* __restrict__ conv_w,
                            const float* __restrict__ w0,
                            const float* __restrict__ w1,
                            float* __restrict__ out) {
    int i = blockIdx.x * blockDim.x + threadIdx.x;

    if (i < BB * NPTS) {
        const int b = i / NPTS;
        const int n = i - b * NPTS;
        float c[8];
        c[0] = xyz[i * 3 + 0];
        c[1] = xyz[i * 3 + 1];
#pragma unroll
        for (int q = 0; q < 6; q++) c[2 + q] = feat[i * 6 + q];

        __half2* lo = reinterpret_cast<__half2*>(g_xfh + ((size_t)(b * 2 + 0) * NPTS + n) * 4);
        __half2* hi = reinterpret_cast<__half2*>(g_xfh + ((size_t)(b * 2 + 1) * NPTS + n) * 4);
        lo[0] = __floats2half2_rn(c[0], c[1]);
        lo[1] = __floats2half2_rn(c[2], c[3]);
        hi[0] = __floats2half2_rn(c[4], c[5]);
        hi[1] = __floats2half2_rn(c[6], c[7]);
    }
    if (i < NITEMS) {
        const int pid = i / 50;
        const int sk  = i - pid * 50;
        const int s   = (sk >= 25) ? 1 : 0;
        const int k   = sk - s * 25;
        const int b   = pid >> 12;
        const int m   = pid & (MM - 1);
        g_base[i] = (((s * BB + b) * MM + m) * KK + k) * JJ;
    }
    if (i < KK * 2 * 64 * 4) {
        int cc = i & 3;
        int o  = (i >> 2) & 63;
        int t  = i >> 8;
        int c4 = t & 1;
        int k  = t >> 1;
        g_cwP[i] = conv_w[o * 200 + (c4 * 4 + cc) * 25 + k];
    }
    if (i < 32 * 128 * 4) {
        int cc = i & 3;
        int o  = (i >> 2) & 127;
        int c4 = i >> 9;
        g_w0P[i] = w0[o * 128 + c4 * 4 + cc];
    }
    if (i < 32 * 256 * 4) {
        int cc = i & 3;
        int o  = (i >> 2) & 255;
        int c4 = i >> 10;
        g_w1P[i] = w1[o * 128 + c4 * 4 + cc];
    }
    if (i < 128) {
        int o = i >> 1, c = i & 1;
        float s = 0.f;
#pragma unroll
        for (int k = 0; k < KK; k++) s += conv_w[o * 200 + c * 25 + k];
        g_wsum[i] = s;
    }
    if (i < BB * MM * 3) {
        out[i] = new_xyz[i];
    }
}

// Pack (idx, weight) into one uint: lo16 = idx, hi16 = fp16 weight
__device__ __forceinline__ unsigned pack_iw(int iv, float wv) {
    return (unsigned)(unsigned short)iv |
           ((unsigned)__half_as_ushort(__float2half_rn(wv)) << 16);
}

// ---------------------------------------------------------------------------
// Gather v9: v8 inner loop, wave-balanced work map.
// 296 blocks = 2 exact waves; per (b,ch) segment 74 blocks take 10-11 passes.
// ---------------------------------------------------------------------------
__global__ __launch_bounds__(GTHR)
void gather_kernel(const int*   __restrict__ idx,
                   const float* __restrict__ weight) {

    extern __shared__ __align__(16) char smem[];
    uint2*    s_tab = reinterpret_cast<uint2*>(smem + SM_TAB);
    unsigned* stg   = reinterpret_cast<unsigned*>(smem + SM_STG + threadIdx.x / 32 * WSTRIDE);

    const int tid  = threadIdx.x;
    const int lane = tid & 31;
    const int blk  = blockIdx.x;
    const int ch   = blk & 1;                 // twins adjacent for L2 dedup
    const int pid  = blk >> 1;                // 0..147
    const int b0   = pid / 74;                // batch
    const int r    = pid - b0 * 74;           // rank within segment
    const int pstart = r * 10 + (r < 60 ? r : 60);
    const int npass  = 10 + (r < 60 ? 1 : 0);

    {
        const uint2* gt = reinterpret_cast<const uint2*>(g_xfh) + (size_t)(b0 * 2 + ch) * NPTS;
        for (int i = tid; i < NPTS; i += GTHR) s_tab[i] = gt[i];
    }
    __syncthreads();

    const int sq  = lane >> 3;
    const int sjl = (lane >> 1) & 3;
    const int seo = (lane & 1) * 2;
    const int woff = sq * QSTRIDE + sjl * 4 + seo;

    const int it  = lane >> 2;
    const int jl4 = lane & 3;
    const unsigned* crow = stg + it * 16 + jl4 * 4;

    // warp's first item of pass q: seg0 + (pstart+q)*256 + warp*8
    const int seg0  = b0 * (MM * 50);
    const int wit0  = seg0 + pstart * IPP + (tid >> 5) * IPW;

    int bc[IPW], bn[IPW];
    uint2 pf[IPW];
    {
#pragma unroll
        for (int t = 0; t < IPW; t++) bc[t] = g_base[wit0 + t];
#pragma unroll
        for (int t = 0; t < IPW; t++) {
            const int2   iv = reinterpret_cast<const int2*>(idx + bc[t])[lane];
            const float2 wv = reinterpret_cast<const float2*>(weight + bc[t])[lane];
            pf[t] = make_uint2(pack_iw(iv.x, wv.x), pack_iw(iv.y, wv.y));
        }
#pragma unroll
        for (int t = 0; t < IPW; t++) bc[t] = g_base[wit0 + IPP + t];
    }

    for (int p = 0; p < npass; p++) {
#pragma unroll
        for (int t = 0; t < IPW; t++)
            *reinterpret_cast<uint2*>(stg + woff + t * 16) = pf[t];
        __syncwarp();

        if (p + 2 < npass) {
            const int nb = wit0 + (p + 2) * IPP;
#pragma unroll
            for (int t = 0; t < IPW; t++) bn[t] = g_base[nb + t];
        }

        if (p + 1 < npass) {
#pragma unroll
            for (int t = 0; t < IPW; t++) {
                const int2   iv = reinterpret_cast<const int2*>(idx + bc[t])[lane];
                const float2 wv = reinterpret_cast<const float2*>(weight + bc[t])[lane];
                pf[t] = make_uint2(pack_iw(iv.x, wv.x), pack_iw(iv.y, wv.y));
            }
        }

        unsigned long long acc01 = 0ull, acc23 = 0ull;
#pragma unroll
        for (int q = 0; q < 4; q++) {
            const uint4 pk = *reinterpret_cast<const uint4*>(crow + q * QSTRIDE);
#pragma unroll
            for (int e = 0; e < 4; e++) {
                const unsigned v = (e == 0) ? pk.x : (e == 1) ? pk.y : (e == 2) ? pk.z : pk.w;
                const uint2 row = s_tab[v & 0xFFFFu];
                const float wv  = __half2float(__ushort_as_half((unsigned short)(v >> 16)));
                const float2 f0 = __half22float2(*reinterpret_cast<const __half2*>(&row.x));
                const float2 f1 = __half22float2(*reinterpret_cast<const __half2*>(&row.y));
                const unsigned long long wp = pack_f32x2(wv, wv);
                acc01 = ffma2_f32x2(wp, pack_f32x2(f0.x, f0.y), acc01);
                acc23 = ffma2_f32x2(wp, pack_f32x2(f1.x, f1.y), acc23);
            }
        }

        float4 acc;
        {
            const float2 a = unpack_f32x2(acc01);
            const float2 b = unpack_f32x2(acc23);
            acc = make_float4(a.x, a.y, b.x, b.y);
        }

#pragma unroll
        for (int msk = 1; msk <= 2; msk <<= 1) {
            acc.x += __shfl_xor_sync(0xffffffffu, acc.x, msk);
            acc.y += __shfl_xor_sync(0xffffffffu, acc.y, msk);
            acc.z += __shfl_xor_sync(0xffffffffu, acc.z, msk);
            acc.w += __shfl_xor_sync(0xffffffffu, acc.w, msk);
        }
        if (jl4 == 0) {
            const int git = wit0 + p * IPP + it;
            *reinterpret_cast<float4*>(g_nf + (size_t)git * 8 + ch * 4) = acc;
        }

#pragma unroll
        for (int t = 0; t < IPW; t++) bc[t] = bn[t];
        __syncwarp();
    }
}

// ---------------------------------------------------------------------------
// Compute kernel (R12, measured 50.1us): point-pair interleave + f32x2.
// ---------------------------------------------------------------------------
__global__ __launch_bounds__(NTHR) void compute_kernel(
    const float* __restrict__ new_xyz,
    const float* __restrict__ conv_b,
    const float* __restrict__ mlp_b0,
    const float* __restrict__ mlp_b1,
    float* __restrict__ out) {

    __shared__ __align__(16) float s_buf2[PTS / 2 * 50 * 16];
    __shared__ __align__(16) float s_x2[PTS / 2 * 128 * 2];
    __shared__ float s_c[PTS * 2];

    const int tid  = threadIdx.x;
    const int warp = tid >> 5;
    const int lane = tid & 31;
    const int blk  = blockIdx.x;

    if (tid < PTS * 2) {
        int p = tid >> 1, c = tid & 1;
        s_c[tid] = new_xyz[(size_t)(blk * PTS + p) * 3 + c];
    }

    {
        const float4* g4 = reinterpret_cast<const float4*>(g_nf) + (size_t)blk * (PTS * 100);
        for (int i = tid; i < PTS * 100; i += NTHR) {
            const float4 v = g4[i];
            const int h  = i & 1;
            const int t  = i >> 1;
            const int p  = t / 50;
            const int sk = t - p * 50;
            float* dst = s_buf2 + ((p >> 1) * 50 + sk) * 16 + h * 8 + (p & 1);
            dst[0] = v.x; dst[2] = v.y; dst[4] = v.z; dst[6] = v.w;
        }
    }
    __syncthreads();

    // ---- Phase B ----
    {
        const int o  = lane + (warp & 1) * 32;
        const int pg = warp >> 1;
        const float4* cw4 = (const float4*)g_cwP;

        const float ws0 = g_wsum[o * 2 + 0];
        const float ws1 = g_wsum[o * 2 + 1];
        const float cb  = conv_b[o];

        unsigned long long acc[SS][2];
#pragma unroll
        for (int q2 = 0; q2 < 2; q2++) {
            const int p2 = pg * 2 + q2;
            const float i0 = cb - ws0 * s_c[(p2 * 2 + 0) * 2 + 0]
                                - ws1 * s_c[(p2 * 2 + 0) * 2 + 1];
            const float i1 = cb - ws0 * s_c[(p2 * 2 + 1) * 2 + 0]
                                - ws1 * s_c[(p2 * 2 + 1) * 2 + 1];
            const unsigned long long init = pack_f32x2(i0, i1);
            acc[0][q2] = init;
            acc[1][q2] = init;
        }

        for (int k = 0; k < KK; k++) {
            const float4 wlo = cw4[(k * 2 + 0) * 64 + o];
            const float4 whi = cw4[(k * 2 + 1) * 64 + o];
            unsigned long long wp[8];
            wp[0] = pack_f32x2(wlo.x, wlo.x);
            wp[1] = pack_f32x2(wlo.y, wlo.y);
            wp[2] = pack_f32x2(wlo.z, wlo.z);
            wp[3] = pack_f32x2(wlo.w, wlo.w);
            wp[4] = pack_f32x2(whi.x, whi.x);
            wp[5] = pack_f32x2(whi.y, whi.y);
            wp[6] = pack_f32x2(whi.z, whi.z);
            wp[7] = pack_f32x2(whi.w, whi.w);
#pragma unroll
            for (int s = 0; s < SS; s++) {
#pragma unroll
                for (int q2 = 0; q2 < 2; q2++) {
                    const int p2 = pg * 2 + q2;
                    const ulonglong2* U = reinterpret_cast<const ulonglong2*>(
                        s_buf2 + (p2 * 50 + s * 25 + k) * 16);
                    const ulonglong2 u0 = U[0];
                    const ulonglong2 u1 = U[1];
                    const ulonglong2 u2 = U[2];
                    const ulonglong2 u3 = U[3];
                    unsigned long long a = acc[s][q2];
                    a = ffma2_f32x2(wp[0], u0.x, a);
                    a = ffma2_f32x2(wp[1], u0.y, a);
                    a = ffma2_f32x2(wp[2], u1.x, a);
                    a = ffma2_f32x2(wp[3], u1.y, a);
                    a = ffma2_f32x2(wp[4], u2.x, a);
                    a = ffma2_f32x2(wp[5], u2.y, a);
                    a = ffma2_f32x2(wp[6], u3.x, a);
                    a = ffma2_f32x2(wp[7], u3.y, a);
                    acc[s][q2] = a;
                }
            }
        }
#pragma unroll
        for (int s = 0; s < SS; s++)
#pragma unroll
            for (int q2 = 0; q2 < 2; q2++) {
                const int p2 = pg * 2 + q2;
                const float2 v = unpack_f32x2(acc[s][q2]);
                *reinterpret_cast<float2*>(s_x2 + (p2 * 128 + s * 64 + o) * 2) =
                    make_float2(fmaxf(v.x, 0.f), fmaxf(v.y, 0.f));
            }
    }
    __syncthreads();

    // ---- Phase C ----
    {
        const int o   = lane + (warp & 3) * 32;
        const int pg2 = warp >> 2;
        const float4* w4 = (const float4*)g_w0P;

        unsigned long long acc[4];
        const unsigned long long binit = pack_f32x2(mlp_b0[o], mlp_b0[o]);
#pragma unroll
        for (int pp = 0; pp < 4; pp++) acc[pp] = binit;

        for (int c4 = 0; c4 < 32; c4++) {
            const float4 wv = w4[c4 * 128 + o];
            unsigned long long wp[4];
            wp[0] = pack_f32x2(wv.x, wv.x);
            wp[1] = pack_f32x2(wv.y, wv.y);
            wp[2] = pack_f32x2(wv.z, wv.z);
            wp[3] = pack_f32x2(wv.w, wv.w);
#pragma unroll
            for (int pp = 0; pp < 4; pp++) {
                const int p2 = pg2 * 4 + pp;
                const ulonglong2* U = reinterpret_cast<const ulonglong2*>(
                    s_x2 + (p2 * 128 + c4 * 4) * 2);
                const ulonglong2 u0 = U[0];
                const ulonglong2 u1 = U[1];
                unsigned long long a = acc[pp];
                a = ffma2_f32x2(wp[0], u0.x, a);
                a = ffma2_f32x2(wp[1], u0.y, a);
                a = ffma2_f32x2(wp[2], u1.x, a);
                a = ffma2_f32x2(wp[3], u1.y, a);
                acc[pp] = a;
            }
        }
#pragma unroll
        for (int pp = 0; pp < 4; pp++) {
            const int p2 = pg2 * 4 + pp;
            const float2 v = unpack_f32x2(acc[pp]);
            *reinterpret_cast<float2*>(s_buf2 + (p2 * 128 + o) * 2) =
                make_float2(fmaxf(v.x, 0.f), fmaxf(v.y, 0.f));
        }
    }
    __syncthreads();

    // ---- Phase D ----
    {
        const int o   = lane + (warp & 3) * 32;
        const int pg2 = warp >> 2;
        const float4* w4 = (const float4*)g_w1P;

        unsigned long long acc0[4], acc1[4];
        const unsigned long long ba = pack_f32x2(mlp_b1[o], mlp_b1[o]);
        const unsigned long long bb = pack_f32x2(mlp_b1[o + 128], mlp_b1[o + 128]);
#pragma unroll
        for (int pp = 0; pp < 4; pp++) { acc0[pp] = ba; acc1[pp] = bb; }

        for (int c4 = 0; c4 < 32; c4++) {
            const float4 wa = w4[c4 * 256 + o];
            const float4 wb = w4[c4 * 256 + o + 128];
            unsigned long long wpa[4], wpb[4];
            wpa[0] = pack_f32x2(wa.x, wa.x);
            wpa[1] = pack_f32x2(wa.y, wa.y);
            wpa[2] = pack_f32x2(wa.z, wa.z);
            wpa[3] = pack_f32x2(wa.w, wa.w);
            wpb[0] = pack_f32x2(wb.x, wb.x);
            wpb[1] = pack_f32x2(wb.y, wb.y);
            wpb[2] = pack_f32x2(wb.z, wb.z);
            wpb[3] = pack_f32x2(wb.w, wb.w);
#pragma unroll
            for (int pp = 0; pp < 4; pp++) {
                const int p2 = pg2 * 4 + pp;
                const ulonglong2* U = reinterpret_cast<const ulonglong2*>(
                    s_buf2 + (p2 * 128 + c4 * 4) * 2);
                const ulonglong2 u0 = U[0];
                const ulonglong2 u1 = U[1];
                unsigned long long a0 = acc0[pp];
                unsigned long long a1 = acc1[pp];
                a0 = ffma2_f32x2(wpa[0], u0.x, a0);
                a1 = ffma2_f32x2(wpb[0], u0.x, a1);
                a0 = ffma2_f32x2(wpa[1], u0.y, a0);
                a1 = ffma2_f32x2(wpb[1], u0.y, a1);
                a0 = ffma2_f32x2(wpa[2], u1.x, a0);
                a1 = ffma2_f32x2(wpb[2], u1.x, a1);
                a0 = ffma2_f32x2(wpa[3], u1.y, a0);
                a1 = ffma2_f32x2(wpb[3], u1.y, a1);
                acc0[pp] = a0;
                acc1[pp] = a1;
            }
        }
        const size_t ob = (size_t)BB * MM * 3;
#pragma unroll
        for (int pp = 0; pp < 4; pp++) {
            const int p2 = pg2 * 4 + pp;
            const int pid0 = blk * PTS + p2 * 2;
            const float2 v0 = unpack_f32x2(acc0[pp]);
            const float2 v1 = unpack_f32x2(acc1[pp]);
            out[ob + (size_t)pid0 * 256 + o]             = fmaxf(v0.x, 0.f);
            out[ob + (size_t)(pid0 + 1) * 256 + o]       = fmaxf(v0.y, 0.f);
            out[ob + (size_t)pid0 * 256 + o + 128]       = fmaxf(v1.x, 0.f);
            out[ob + (size_t)(pid0 + 1) * 256 + o + 128] = fmaxf(v1.y, 0.f);
        }
    }
}

// ---------------------------------------------------------------------------
extern "C" void kernel_launch(void* const* d_in, const int* in_sizes, int n_in,
                              void* d_out, int out_size) {
    const float* xyz     = (const float*)d_in[0];
    const float* feature = (const float*)d_in[1];
    const float* new_xyz = (const float*)d_in[2];
    const int*   idx     = (const int*)  d_in[3];
    const float* weight  = (const float*)d_in[4];
    const float* conv_w  = (const float*)d_in[5];
    const float* conv_b  = (const float*)d_in[6];
    const float* mlp_w0  = (const float*)d_in[7];
    const float* mlp_b0  = (const float*)d_in[8];
    const float* mlp_w1  = (const float*)d_in[9];
    const float* mlp_b1  = (const float*)d_in[10];
    float* out = (float*)d_out;

    (void)in_sizes; (void)n_in; (void)out_size;

    cudaFuncSetAttribute(gather_kernel,
                         cudaFuncAttributeMaxDynamicSharedMemorySize,
                         SM_TOTAL);

    prep_kernel<<<(NITEMS + NTHR - 1) / NTHR, NTHR>>>(
        xyz, feature, new_xyz, conv_w, mlp_w0, mlp_w1, out);

    gather_kernel<<<GBLKS, GTHR, SM_TOTAL>>>(idx, weight);

    compute_kernel<<<(BB * MM) / PTS, NTHR>>>(
        new_xyz, conv_b, mlp_b0, mlp_b1, out);
}